// round 16
// baseline (speedup 1.0000x reference)
#include <cuda_runtime.h>
#include <cuda_bf16.h>
#include <math.h>

#define SN 1536
#define SD 512
#define SH 4
#define SDH 128
#define SNI 5
#define SNL 3
#define QPW_LD 514
#define NCAT 1408
#define ISQ 0.0883883476483184405f

typedef unsigned int u32;
typedef __nv_bfloat16 bf16;

// ---------------- static scratch (sizes in floats) ----------------
#define SZ_XH    (SN*SD/2)
#define SZ_QKV   (SN*3*SD)
#define SZ_QKH   (SN*1024/2)
#define SZ_S     (SH*SN*SN/2)
#define SZ_VTH   (SH*SDH*SN/2)
#define SZ_RS    (SH*SN)
#define SZ_O1    (SN*SD)
#define SZ_O1H   (SN*SD/2)
#define SZ_AO    (SN*SD)
#define SZ_AOH   (SN*SD/2)
#define SZ_E     (SH*SN*SN/2)
#define SZ_CAT   (SN*NCAT)
#define SZ_CQH   (SN*1024/2)
#define SZ_LG    (SNI*SN*200)
#define SZ_SOFF  (SNI*SN)
#define SZ_AL    (SH*SN)
#define SZ_V512  (SD)
#define SZ_QPT   (SD*SD)
#define SZ_WC    (SD*SD)
#define SZ_WPH   (NCAT*SD/2)
#define SZ_PB    (NCAT)
#define SZ_INWH  (3*SD*SD/2)
#define SZ_OWH   (SD*SD/2)
#define SZ_RW2H  (SNL*200*128/2)
#define SZ_W56   (2*SNL*128)
#define SZ_MISC  (32)

#define OFF_XH    0
#define OFF_XL    (OFF_XH + SZ_XH)
#define OFF_QKV   (OFF_XL + SZ_XH)
#define OFF_QKH   (OFF_QKV + SZ_QKV)
#define OFF_QKL   (OFF_QKH + SZ_QKH)
#define OFF_S     (OFF_QKL + SZ_QKH)
#define OFF_VTH   (OFF_S + SZ_S)
#define OFF_VTL   (OFF_VTH + SZ_VTH)
#define OFF_RS    (OFF_VTL + SZ_VTH)
#define OFF_O1    (OFF_RS + SZ_RS)
#define OFF_O1H   (OFF_O1 + SZ_O1)
#define OFF_O1L   (OFF_O1H + SZ_O1H)
#define OFF_AO    (OFF_O1L + SZ_O1H)
#define OFF_AOH   (OFF_AO + SZ_AO)
#define OFF_AOL   (OFF_AOH + SZ_AOH)
#define OFF_E     (OFF_AOL + SZ_AOH)
#define OFF_CAT   (OFF_E + SZ_E)
#define OFF_CQH   (OFF_CAT + SZ_CAT)
#define OFF_CQL   (OFF_CQH + SZ_CQH)
#define OFF_LG    (OFF_CQL + SZ_CQH)
#define OFF_SOFF  (OFF_LG + SZ_LG)
#define OFF_EOFF  (OFF_SOFF + SZ_SOFF)
#define OFF_AL    (OFF_EOFF + SZ_SOFF)
#define OFF_BE    (OFF_AL + SZ_AL)
#define OFF_A     (OFF_BE + SZ_AL)
#define OFF_B     (OFF_A + SZ_V512)
#define OFF_QBIAS (OFF_B + SZ_V512)
#define OFF_POOL  (OFF_QBIAS + SZ_V512)
#define OFF_QPT   (OFF_POOL + SZ_V512)
#define OFF_WC    (OFF_QPT + SZ_QPT)
#define OFF_WPH   (OFF_WC + SZ_WC)
#define OFF_WPL   (OFF_WPH + SZ_WPH)
#define OFF_PB    (OFF_WPL + SZ_WPH)
#define OFF_INWH  (OFF_PB + SZ_PB)
#define OFF_INWL  (OFF_INWH + SZ_INWH)
#define OFF_OWH   (OFF_INWL + SZ_INWH)
#define OFF_OWL   (OFF_OWH + SZ_OWH)
#define OFF_RW2H  (OFF_OWL + SZ_OWH)
#define OFF_RW2L  (OFF_RW2H + SZ_RW2H)
#define OFF_W56   (OFF_RW2L + SZ_RW2H)
#define OFF_MISC  (OFF_W56 + SZ_W56)
#define BUF_TOTAL (OFF_MISC + SZ_MISC)

__device__ float g_buf[BUF_TOTAL];

// misc: 0 tmin, 1 tmax, [2..6] start, [7..11] end, [12..16] ds, [17..21] de, 22 counter

// ---------------- MMA helpers ----------------
__device__ __forceinline__ u32 smem_u32(const void* p) {
    u32 a;
    asm("{ .reg .u64 t; cvta.to.shared.u64 t, %1; cvt.u32.u64 %0, t; }" : "=r"(a) : "l"(p));
    return a;
}
__device__ __forceinline__ void ldsm4(u32* r, u32 addr) {
    asm volatile("ldmatrix.sync.aligned.m8n8.x4.shared.b16 {%0,%1,%2,%3}, [%4];"
                 : "=r"(r[0]), "=r"(r[1]), "=r"(r[2]), "=r"(r[3]) : "r"(addr));
}
__device__ __forceinline__ void mma16816(float* c, const u32* a, const u32* b) {
    asm volatile(
        "mma.sync.aligned.m16n8k16.row.col.f32.bf16.bf16.f32 "
        "{%0,%1,%2,%3}, {%4,%5,%6,%7}, {%8,%9}, {%0,%1,%2,%3};"
        : "+f"(c[0]), "+f"(c[1]), "+f"(c[2]), "+f"(c[3])
        : "r"(a[0]), "r"(a[1]), "r"(a[2]), "r"(a[3]), "r"(b[0]), "r"(b[1]));
}
__device__ __forceinline__ void split4(float4 v, uint2& hi, uint2& lo) {
    bf16 h0 = __float2bfloat16_rn(v.x), h1 = __float2bfloat16_rn(v.y),
         h2 = __float2bfloat16_rn(v.z), h3 = __float2bfloat16_rn(v.w);
    __nv_bfloat162 hp0 = __halves2bfloat162(h0, h1), hp1 = __halves2bfloat162(h2, h3);
    __nv_bfloat162 lp0 = __floats2bfloat162_rn(v.x - __bfloat162float(h0),
                                               v.y - __bfloat162float(h1));
    __nv_bfloat162 lp1 = __floats2bfloat162_rn(v.z - __bfloat162float(h2),
                                               v.w - __bfloat162float(h3));
    hi = make_uint2(*(u32*)&hp0, *(u32*)&hp1);
    lo = make_uint2(*(u32*)&lp0, *(u32*)&lp1);
}

// ---------------- tensor-core NT GEMM ----------------
// MODE 0: plain (bias if ksplit==1 else atomic); MODE 1: C(bf16)=exp(scale*acc),
// row-sum atomics to rsbuf; MODE 2: C += (scale/rsbuf[r])*acc atomic;
// MODE 3: A-load relu(A + s*hb5 + e*hb6) (AP must be 0).
// AP/BP: 0 = fp32 source (split on the fly), 1 = pre-split hi/lo bf16 planes,
//        2 = exact bf16 (A only; 2-term MMA).
#define LDT 40
template<int MODE>
__device__ __forceinline__ float4 ldA4(const float* p, int kcol,
                                       const float* hb5, const float* hb6,
                                       float s, float e) {
    float4 v = *(const float4*)p;
    if (MODE == 3) {
        float4 w5 = *(const float4*)(hb5 + kcol);
        float4 w6 = *(const float4*)(hb6 + kcol);
        v.x = fmaxf(v.x + s * w5.x + e * w6.x, 0.f);
        v.y = fmaxf(v.y + s * w5.y + e * w6.y, 0.f);
        v.z = fmaxf(v.z + s * w5.z + e * w6.z, 0.f);
        v.w = fmaxf(v.w + s * w5.w + e * w6.w, 0.f);
    }
    return v;
}

template<int MODE, int AP, int BP>
__global__ void __launch_bounds__(256)
tgemm(int M, int N, int K,
      const void* __restrict__ Apv, const void* __restrict__ Alov, int lda, long sA,
      const void* __restrict__ Bpv, const void* __restrict__ Blov, int ldb, long sB,
      const float* __restrict__ bias,
      float* __restrict__ C, int ldc, long sC,
      float scale, int ksplit,
      float* __restrict__ rsbuf, long sRS,
      const float* __restrict__ hb5, const float* __restrict__ hb6,
      const float* __restrict__ misc) {
    __shared__ bf16 sA_[2][128 * LDT];
    __shared__ bf16 sB_[2][64 * LDT];

    int batch = blockIdx.z / ksplit;
    int kz = blockIdx.z % ksplit;
    int Kc = K / ksplit;
    int kbeg = kz * Kc;

    const float* Af = (AP == 0) ? (const float*)Apv + (long)batch * sA : nullptr;
    const bf16* Ah = (AP != 0) ? (const bf16*)Apv + (long)batch * sA : nullptr;
    const bf16* Al = (AP == 1) ? (const bf16*)Alov + (long)batch * sA : nullptr;
    const float* Bf = (BP == 0) ? (const float*)Bpv + (long)batch * sB : nullptr;
    const bf16* Bh = (BP == 1) ? (const bf16*)Bpv + (long)batch * sB : nullptr;
    const bf16* Bl = (BP == 1) ? (const bf16*)Blov + (long)batch * sB : nullptr;
    bf16* Cb = nullptr;
    if (MODE == 1) Cb = (bf16*)C + (long)batch * sC;
    else C += (long)batch * sC;
    int brow = blockIdx.y * 128, bcol = blockIdx.x * 64;

    float hs = 0.f, he = 0.f;
    if (MODE == 3) { hs = misc[2 + batch]; he = misc[7 + batch]; }

    int tid = threadIdx.x;
    int wid = tid >> 5, lane = tid & 31;
    int wm = (wid & 3) * 32;
    int wn = (wid >> 2) * 32;

    u32 aBase[2] = { smem_u32(sA_[0]), smem_u32(sA_[1]) };
    u32 bBase[2] = { smem_u32(sB_[0]), smem_u32(sB_[1]) };

    int rowsel = (lane & 7) + ((lane >> 3) & 1) * 8;
    int ksel = (lane >> 4) * 8;

    float acc[2][4][4];
#pragma unroll
    for (int mi = 0; mi < 2; mi++)
#pragma unroll
        for (int ni = 0; ni < 4; ni++)
#pragma unroll
            for (int j = 0; j < 4; j++) acc[mi][ni][j] = 0.f;

    float4 pa[4], pb[2];
    uint2 pah[4], pal[4], pbh[2], pbl[2];
#pragma unroll
    for (int i = 0; i < 4; i++) {
        int idx = tid + i * 256;
        int row = idx >> 3, col = (idx & 7) * 4;
        if (AP == 0)
            pa[i] = ldA4<MODE>(Af + (long)(brow + row) * lda + kbeg + col, kbeg + col,
                               hb5, hb6, hs, he);
        else {
            pah[i] = *(const uint2*)(Ah + (long)(brow + row) * lda + kbeg + col);
            if (AP == 1) pal[i] = *(const uint2*)(Al + (long)(brow + row) * lda + kbeg + col);
        }
    }
#pragma unroll
    for (int i = 0; i < 2; i++) {
        int idx = tid + i * 256;
        int row = idx >> 3, col = (idx & 7) * 4;
        int rB = bcol + row;
        if (rB < N) {
            if (BP == 0) pb[i] = *(const float4*)(Bf + (long)rB * ldb + kbeg + col);
            else {
                pbh[i] = *(const uint2*)(Bh + (long)rB * ldb + kbeg + col);
                pbl[i] = *(const uint2*)(Bl + (long)rB * ldb + kbeg + col);
            }
        } else {
            if (BP == 0) pb[i] = make_float4(0.f, 0.f, 0.f, 0.f);
            else { pbh[i] = make_uint2(0u, 0u); pbl[i] = make_uint2(0u, 0u); }
        }
    }

    for (int kc = 0; kc < Kc; kc += 32) {
#pragma unroll
        for (int i = 0; i < 4; i++) {
            int idx = tid + i * 256;
            int row = idx >> 3, col = (idx & 7) * 4;
            if (AP == 0) {
                uint2 hi, lo;
                split4(pa[i], hi, lo);
                *(uint2*)&sA_[0][row * LDT + col] = hi;
                *(uint2*)&sA_[1][row * LDT + col] = lo;
            } else {
                *(uint2*)&sA_[0][row * LDT + col] = pah[i];
                if (AP == 1) *(uint2*)&sA_[1][row * LDT + col] = pal[i];
            }
        }
#pragma unroll
        for (int i = 0; i < 2; i++) {
            int idx = tid + i * 256;
            int row = idx >> 3, col = (idx & 7) * 4;
            if (BP == 0) {
                uint2 hi, lo;
                split4(pb[i], hi, lo);
                *(uint2*)&sB_[0][row * LDT + col] = hi;
                *(uint2*)&sB_[1][row * LDT + col] = lo;
            } else {
                *(uint2*)&sB_[0][row * LDT + col] = pbh[i];
                *(uint2*)&sB_[1][row * LDT + col] = pbl[i];
            }
        }
        __syncthreads();

        int kn = kbeg + kc + 32;
        if (kc + 32 < Kc) {
#pragma unroll
            for (int i = 0; i < 4; i++) {
                int idx = tid + i * 256;
                int row = idx >> 3, col = (idx & 7) * 4;
                if (AP == 0)
                    pa[i] = ldA4<MODE>(Af + (long)(brow + row) * lda + kn + col, kn + col,
                                       hb5, hb6, hs, he);
                else {
                    pah[i] = *(const uint2*)(Ah + (long)(brow + row) * lda + kn + col);
                    if (AP == 1) pal[i] = *(const uint2*)(Al + (long)(brow + row) * lda + kn + col);
                }
            }
#pragma unroll
            for (int i = 0; i < 2; i++) {
                int idx = tid + i * 256;
                int row = idx >> 3, col = (idx & 7) * 4;
                int rB = bcol + row;
                if (rB < N) {
                    if (BP == 0) pb[i] = *(const float4*)(Bf + (long)rB * ldb + kn + col);
                    else {
                        pbh[i] = *(const uint2*)(Bh + (long)rB * ldb + kn + col);
                        pbl[i] = *(const uint2*)(Bl + (long)rB * ldb + kn + col);
                    }
                } else {
                    if (BP == 0) pb[i] = make_float4(0.f, 0.f, 0.f, 0.f);
                    else { pbh[i] = make_uint2(0u, 0u); pbl[i] = make_uint2(0u, 0u); }
                }
            }
        }

#pragma unroll
        for (int ks = 0; ks < 32; ks += 16) {
            u32 ahi[2][4], alo[2][4], bhi[4][2], blo[4][2];
#pragma unroll
            for (int mi = 0; mi < 2; mi++) {
                u32 off = ((wm + mi * 16 + rowsel) * LDT + ks + ksel) * 2;
                ldsm4(ahi[mi], aBase[0] + off);
                if (AP != 2) ldsm4(alo[mi], aBase[1] + off);
            }
#pragma unroll
            for (int nj = 0; nj < 2; nj++) {
                u32 off = ((wn + nj * 16 + rowsel) * LDT + ks + ksel) * 2;
                u32 t0[4], t1[4];
                ldsm4(t0, bBase[0] + off);
                ldsm4(t1, bBase[1] + off);
                bhi[2 * nj][0] = t0[0]; bhi[2 * nj][1] = t0[2];
                bhi[2 * nj + 1][0] = t0[1]; bhi[2 * nj + 1][1] = t0[3];
                blo[2 * nj][0] = t1[0]; blo[2 * nj][1] = t1[2];
                blo[2 * nj + 1][0] = t1[1]; blo[2 * nj + 1][1] = t1[3];
            }
#pragma unroll
            for (int mi = 0; mi < 2; mi++)
#pragma unroll
                for (int ni = 0; ni < 4; ni++) {
                    mma16816(acc[mi][ni], ahi[mi], bhi[ni]);
                    mma16816(acc[mi][ni], ahi[mi], blo[ni]);
                    if (AP != 2) mma16816(acc[mi][ni], alo[mi], bhi[ni]);
                }
        }
        __syncthreads();
    }

    // epilogue
    int g = lane >> 2, t = lane & 3;
#pragma unroll
    for (int mi = 0; mi < 2; mi++) {
        int r0 = brow + wm + mi * 16 + g;
        int r1 = r0 + 8;
        float s0 = scale, s1 = scale;
        if (MODE == 2) {
            s0 = scale / rsbuf[sRS * batch + r0];
            s1 = scale / rsbuf[sRS * batch + r1];
        }
        float sum0 = 0.f, sum1 = 0.f;
#pragma unroll
        for (int ni = 0; ni < 4; ni++) {
            int cc = bcol + wn + ni * 8 + 2 * t;
            float v00 = acc[mi][ni][0] * s0, v01 = acc[mi][ni][1] * s0;
            float v10 = acc[mi][ni][2] * s1, v11 = acc[mi][ni][3] * s1;
            if (MODE == 1) {
                v00 = __expf(v00); v01 = __expf(v01);
                v10 = __expf(v10); v11 = __expf(v11);
                sum0 += v00 + v01; sum1 += v10 + v11;
                if (cc < N) {
                    __nv_bfloat162 p0 = __floats2bfloat162_rn(v00, v01);
                    __nv_bfloat162 p1 = __floats2bfloat162_rn(v10, v11);
                    *(u32*)&Cb[(long)r0 * ldc + cc] = *(u32*)&p0;
                    *(u32*)&Cb[(long)r1 * ldc + cc] = *(u32*)&p1;
                }
            } else if (MODE == 2 || ksplit > 1) {
                if (cc < N) {
                    atomicAdd(&C[(long)r0 * ldc + cc], v00);
                    atomicAdd(&C[(long)r1 * ldc + cc], v10);
                }
                if (cc + 1 < N) {
                    atomicAdd(&C[(long)r0 * ldc + cc + 1], v01);
                    atomicAdd(&C[(long)r1 * ldc + cc + 1], v11);
                }
            } else {
                if (bias) {
                    if (cc < N) { v00 += bias[cc]; v10 += bias[cc]; }
                    if (cc + 1 < N) { v01 += bias[cc + 1]; v11 += bias[cc + 1]; }
                }
                if (cc < N) { C[(long)r0 * ldc + cc] = v00; C[(long)r1 * ldc + cc] = v10; }
                if (cc + 1 < N) { C[(long)r0 * ldc + cc + 1] = v01; C[(long)r1 * ldc + cc + 1] = v11; }
            }
        }
        if (MODE == 1 && rsbuf) {
            sum0 += __shfl_xor_sync(0xffffffffu, sum0, 1);
            sum0 += __shfl_xor_sync(0xffffffffu, sum0, 2);
            sum1 += __shfl_xor_sync(0xffffffffu, sum1, 1);
            sum1 += __shfl_xor_sync(0xffffffffu, sum1, 2);
            if (t == 0) {
                atomicAdd(&rsbuf[sRS * batch + r0], sum0);
                atomicAdd(&rsbuf[sRS * batch + r1], sum1);
            }
        }
    }
}

// ---------------- split helpers ----------------
__global__ void k_split(const float* __restrict__ src, bf16* __restrict__ dh,
                        bf16* __restrict__ dl, int n4) {
    int i = blockIdx.x * 256 + threadIdx.x;
    if (i < n4) {
        float4 v = ((const float4*)src)[i];
        uint2 hi, lo;
        split4(v, hi, lo);
        ((uint2*)dh)[i] = hi;
        ((uint2*)dl)[i] = lo;
    }
}
// strided source: rows x 1024, src row stride lds; dst ld 1024
__global__ void k_split_st(const float* __restrict__ src, int lds,
                           bf16* __restrict__ dh, bf16* __restrict__ dl, int n4) {
    int i = blockIdx.x * 256 + threadIdx.x;
    if (i < n4) {
        int row = i >> 8;
        int c4 = (i & 255) << 2;
        float4 v = *(const float4*)(src + (long)row * lds + c4);
        uint2 hi, lo;
        split4(v, hi, lo);
        long o = ((long)row << 8) + (i & 255);
        ((uint2*)dh)[o] = hi;
        ((uint2*)dl)[o] = lo;
    }
}

// ---------------- small kernels ----------------

// X = ne + t*Wt^T + bt, written as bf16 hi/lo planes; zero pool + RS
__global__ void k_x(const float* __restrict__ ne, const float* __restrict__ tp,
                    const float* __restrict__ wt, const float* __restrict__ bt,
                    bf16* __restrict__ XH, bf16* __restrict__ XL,
                    float* __restrict__ pool, float* __restrict__ RS) {
    int i = blockIdx.x * 256 + threadIdx.x;
    if (i < SN * SD / 4) {
        int row = (i << 2) >> 9, d0 = (i << 2) & 511;
        float tv = tp[row];
        float4 n4 = ((const float4*)ne)[i];
        float4 w4 = *(const float4*)(wt + d0);
        float4 b4 = *(const float4*)(bt + d0);
        float4 v = make_float4(n4.x + tv * w4.x + b4.x, n4.y + tv * w4.y + b4.y,
                               n4.z + tv * w4.z + b4.z, n4.w + tv * w4.w + b4.w);
        uint2 hi, lo;
        split4(v, hi, lo);
        ((uint2*)XH)[i] = hi;
        ((uint2*)XL)[i] = lo;
    }
    if (i < SD) pool[i] = 0.f;
    if (i < SH * SN) RS[i] = 0.f;
}

__global__ void k_qpt(const float* __restrict__ qp_w, float* __restrict__ QPT) {
    __shared__ float t[32][33];
    int d0 = blockIdx.x * 32, j0 = blockIdx.y * 32;
    int x = threadIdx.x, y0 = threadIdx.y;
#pragma unroll
    for (int dy = 0; dy < 32; dy += 8) {
        int d = d0 + y0 + dy;
        t[y0 + dy][x] = qp_w[(long)d * QPW_LD + j0 + x];
    }
    __syncthreads();
#pragma unroll
    for (int dy = 0; dy < 32; dy += 8) {
        int j = j0 + y0 + dy;
        QPT[(long)j * SD + d0 + x] = t[x][y0 + dy];
    }
}

__global__ void k_ab(const float* __restrict__ in_w, const float* __restrict__ qp_w,
                     const float* __restrict__ qp_b, const float* __restrict__ in_b,
                     float* __restrict__ a, float* __restrict__ b,
                     float* __restrict__ qbias) {
    __shared__ float u[SD], v[SD], w[SD];
    int tid = threadIdx.x;  // 512
    u[tid] = qp_w[(long)tid * QPW_LD + 512];
    v[tid] = qp_w[(long)tid * QPW_LD + 513];
    w[tid] = qp_b[tid];
    __syncthreads();
    float sa = 0.f, sb = 0.f, sq = 0.f;
    const float* wr = in_w + (long)tid * SD;
    for (int d = 0; d < SD; d++) {
        float ww = wr[d];
        sa += ww * u[d];
        sb += ww * v[d];
        sq += ww * w[d];
    }
    a[tid] = sa; b[tid] = sb; qbias[tid] = in_b[tid] + sq;
}

// pack WP (bf16 hi/lo), PB, W56
__global__ void k_pack(const float* __restrict__ in_w, const float* __restrict__ in_b,
                       const float* __restrict__ WC, const float* __restrict__ qbias,
                       const float* __restrict__ ref_w1, const float* __restrict__ ref_b1,
                       bf16* __restrict__ WPH, bf16* __restrict__ WPL,
                       float* __restrict__ PB, float* __restrict__ w56) {
    int idx = blockIdx.x * 256 + threadIdx.x;
    if (idx < NCAT * SD) {
        int n = idx >> 9, d = idx & 511;
        float v;
        if (n < SD) v = in_w[(long)(SD + n) * SD + d];
        else if (n < 2 * SD) v = WC[(long)(n - SD) * SD + d];
        else v = ref_w1[(long)(n - 2 * SD) * QPW_LD + d];
        bf16 h = __float2bfloat16_rn(v);
        WPH[idx] = h;
        WPL[idx] = __float2bfloat16_rn(v - __bfloat162float(h));
    }
    if (idx < NCAT) {
        float v;
        if (idx < SD) v = in_b[SD + idx];
        else if (idx < 2 * SD) v = qbias[idx - SD];
        else v = ref_b1[idx - 2 * SD];
        PB[idx] = v;
    }
    if (idx < SNL * 128) {
        w56[idx] = ref_w1[(long)idx * QPW_LD + 512];
        w56[SNL * 128 + idx] = ref_w1[(long)idx * QPW_LD + 513];
    }
}

__global__ void k_init2(float* __restrict__ O1, float* __restrict__ AO,
                        const float* __restrict__ out_b) {
    int idx = blockIdx.x * 256 + threadIdx.x;
    if (idx < SN * SD) {
        O1[idx] = 0.f;
        AO[idx] = out_b[idx & 511];
    }
}

// V transpose, writing bf16 hi/lo planes
__global__ void k_vt(const float* __restrict__ QKV, bf16* __restrict__ VTH,
                     bf16* __restrict__ VTL) {
    __shared__ float t[32][33];
    int h = blockIdx.z;
    int k0 = blockIdx.x * 32, n0 = blockIdx.y * 32;
    int x = threadIdx.x, y0 = threadIdx.y;
#pragma unroll
    for (int dy = 0; dy < 32; dy += 8) {
        int k = k0 + y0 + dy;
        t[y0 + dy][x] = QKV[(long)k * (3 * SD) + 2 * SD + h * SDH + n0 + x];
    }
    __syncthreads();
#pragma unroll
    for (int dy = 0; dy < 32; dy += 8) {
        int n = n0 + y0 + dy;
        float v = t[x][y0 + dy];
        bf16 hh = __float2bfloat16_rn(v);
        long o = ((long)h * SDH + n) * SN + k0 + x;
        VTH[o] = hh;
        VTL[o] = __float2bfloat16_rn(v - __bfloat162float(hh));
    }
}

__global__ void k_pool(const float* __restrict__ AO, float* __restrict__ pool) {
    int d = threadIdx.x;  // 512
    int r0 = blockIdx.x * 128;
    float s = 0.f;
    for (int r = 0; r < 128; r++) s += AO[(long)(r0 + r) * SD + d];
    atomicAdd(&pool[d], s);
}

__global__ void k_cls(const float* __restrict__ pool,
                      const float* __restrict__ w1, const float* __restrict__ b1,
                      const float* __restrict__ w2, const float* __restrict__ b2,
                      float* __restrict__ out, int out_size) {
    __shared__ float pv[SD];
    __shared__ float h1[128];
    __shared__ float lg[5];
    int tid = threadIdx.x;  // 128
    for (int i = tid; i < SD; i += 128) pv[i] = pool[i] * (1.f / SN);
    __syncthreads();
    {
        float r = b1[tid];
        const float* wr = w1 + (long)tid * SD;
        for (int d = 0; d < SD; d++) r += wr[d] * pv[d];
        h1[tid] = fmaxf(r, 0.f);
    }
    __syncthreads();
    if (tid < 5) {
        float r = b2[tid];
        const float* wr = w2 + (long)tid * 128;
        for (int j = 0; j < 128; j++) r += wr[j] * h1[j];
        lg[tid] = r;
    }
    __syncthreads();
    if (tid == 0) {
        int arg = 0;
        float best = lg[0];
        for (int i = 1; i < 5; i++)
            if (lg[i] > best) { best = lg[i]; arg = i; }
        int num = arg + 1;
        if (out_size >= 15)
            for (int i = 0; i < 5; i++) out[10 + i] = (i < num) ? 1.f : 0.f;
    }
}

__global__ void k_tmm(const float* __restrict__ tp, float* __restrict__ misc) {
    __shared__ float mn[256], mx[256];
    int tid = threadIdx.x;
    float a = 1e30f, b = -1e30f;
    for (int i = tid; i < SN; i += 256) {
        float v = tp[i];
        a = fminf(a, v);
        b = fmaxf(b, v);
    }
    mn[tid] = a; mx[tid] = b;
    __syncthreads();
    for (int s = 128; s > 0; s >>= 1) {
        if (tid < s) {
            mn[tid] = fminf(mn[tid], mn[tid + s]);
            mx[tid] = fmaxf(mx[tid], mx[tid + s]);
        }
        __syncthreads();
    }
    if (tid == 0) {
        float tmin = mn[0], tmax = mx[0];
        misc[0] = tmin; misc[1] = tmax;
        float step = (tmax - tmin) / 5.f;
        for (int i = 0; i < 5; i++) {
            misc[2 + i] = tmin + i * step;
            misc[7 + i] = tmin + (i + 1) * step;
        }
        misc[22] = 0.f;
    }
    if (tid >= 32 && tid < 42) misc[12 + (tid - 32)] = 0.f;
}

__global__ void k_alphabeta(const float* __restrict__ a, const float* __restrict__ b,
                            const float* __restrict__ K2, int ldk,
                            float* __restrict__ alpha, float* __restrict__ beta) {
    int h = blockIdx.y;
    int k = blockIdx.x * 256 + threadIdx.x;
    __shared__ float a_s[SDH], b_s[SDH];
    if (threadIdx.x < SDH) {
        a_s[threadIdx.x] = a[h * SDH + threadIdx.x];
        b_s[threadIdx.x] = b[h * SDH + threadIdx.x];
    }
    __syncthreads();
    if (k >= SN) return;
    const float* kr = K2 + (long)k * ldk + h * SDH;
    float sa = 0.f, sb = 0.f;
    for (int j = 0; j < SDH; j++) {
        float kv = kr[j];
        sa += kv * a_s[j];
        sb += kv * b_s[j];
    }
    alpha[h * SN + k] = sa * ISQ;
    beta[h * SN + k] = sb * ISQ;
}

__global__ void k_soff(const float* __restrict__ LG, const float* __restrict__ wp,
                       float* __restrict__ SOFF, float* __restrict__ EOFF) {
    int r = blockIdx.x;
    int warp = threadIdx.x >> 5, lane = threadIdx.x & 31;
    const float* row = LG + (long)r * 200 + warp * 100;
    float m = -1e30f;
    for (int k = lane; k < 100; k += 32) m = fmaxf(m, row[k]);
    for (int o = 16; o > 0; o >>= 1) m = fmaxf(m, __shfl_xor_sync(0xffffffffu, m, o));
    float s = 0.f, d = 0.f;
    for (int k = lane; k < 100; k += 32) {
        float e = __expf(row[k] - m);
        s += e;
        d += e * wp[k];
    }
    for (int o = 16; o > 0; o >>= 1) {
        s += __shfl_xor_sync(0xffffffffu, s, o);
        d += __shfl_xor_sync(0xffffffffu, d, o);
    }
    if (lane == 0) {
        float val = d / s;
        if (warp == 0) SOFF[r] = val; else EOFF[r] = val;
    }
}

__global__ void k_accum2(const bf16* __restrict__ E,
                         const float* __restrict__ AL, const float* __restrict__ BE,
                         const float* __restrict__ SOFF, const float* __restrict__ EOFF,
                         float* __restrict__ misc, int nblocks) {
    int h = blockIdx.y;
    int warp = threadIdx.x >> 5, lane = threadIdx.x & 31;
    int q = blockIdx.x * 16 + warp;
    __shared__ float Gs[15][256];
    __shared__ float se[10];
    __shared__ int lastflag;
    if (threadIdx.x < 10) se[threadIdx.x] = misc[2 + threadIdx.x];
    const bf16* Erow = E + (long)h * SN * SN + (long)q * SN;
    float acc[15];
#pragma unroll
    for (int c = 0; c < 15; c++) acc[c] = 0.f;
    for (int k0 = 0; k0 < SN; k0 += 256) {
        __syncthreads();
        for (int idx = threadIdx.x; idx < 5 * 256; idx += 512) {
            int i = idx >> 8, kk = idx & 255;
            int k = k0 + kk;
            float al = AL[h * SN + k], be = BE[h * SN + k];
            float g = __expf(se[i] * al + se[5 + i] * be);
            Gs[3 * i][kk] = g;
            Gs[3 * i + 1][kk] = g * SOFF[i * SN + k];
            Gs[3 * i + 2][kk] = g * EOFF[i * SN + k];
        }
        __syncthreads();
#pragma unroll
        for (int s = 0; s < 8; s++) {
            int kk = lane + 32 * s;
            float ev = __bfloat162float(Erow[k0 + kk]);
#pragma unroll
            for (int c = 0; c < 15; c++) acc[c] += ev * Gs[c][kk];
        }
    }
#pragma unroll
    for (int c = 0; c < 15; c++)
        for (int o = 16; o > 0; o >>= 1)
            acc[c] += __shfl_xor_sync(0xffffffffu, acc[c], o);
    if (lane == 0) {
#pragma unroll
        for (int i = 0; i < 5; i++) {
            float inv = 0.25f / acc[3 * i];
            atomicAdd(&misc[12 + i], acc[3 * i + 1] * inv);
            atomicAdd(&misc[17 + i], acc[3 * i + 2] * inv);
        }
    }
    __syncthreads();
    if (threadIdx.x == 0) {
        __threadfence();
        u32 old = atomicAdd((u32*)&misc[22], 1u);
        lastflag = (old == (u32)(nblocks - 1)) ? 1 : 0;
    }
    __syncthreads();
    if (lastflag && threadIdx.x < 5) {
        int t = threadIdx.x;
        misc[2 + t] += misc[12 + t];
        misc[7 + t] += misc[17 + t];
        misc[12 + t] = 0.f;
        misc[17 + t] = 0.f;
        if (t == 0) misc[22] = 0.f;
    }
}

__global__ void k_outb(const float* __restrict__ misc, float* __restrict__ out, int out_size) {
    int t = threadIdx.x;
    if (t < 5 && out_size >= 10) {
        out[2 * t] = misc[2 + t];
        out[2 * t + 1] = misc[7 + t];
    }
}

// ---------------- host ----------------
extern "C" void kernel_launch(void* const* d_in, const int* in_sizes, int n_in,
                              void* d_out, int out_size) {
    const float* ne     = (const float*)d_in[0];
    const float* tp     = (const float*)d_in[1];
    const float* W_time = (const float*)d_in[3];
    const float* b_time = (const float*)d_in[4];
    const float* in_w   = (const float*)d_in[5];
    const float* in_b   = (const float*)d_in[6];
    const float* out_w  = (const float*)d_in[7];
    const float* out_b  = (const float*)d_in[8];
    const float* ic_w1  = (const float*)d_in[9];
    const float* ic_b1  = (const float*)d_in[10];
    const float* ic_w2  = (const float*)d_in[11];
    const float* ic_b2  = (const float*)d_in[12];
    const float* ref_w1 = (const float*)d_in[13];
    const float* ref_b1 = (const float*)d_in[14];
    const float* ref_w2 = (const float*)d_in[15];
    const float* ref_b2 = (const float*)d_in[16];
    const float* wp     = (const float*)d_in[17];
    const float* qp_w   = (const float*)d_in[18];
    const float* qp_b   = (const float*)d_in[19];
    float* out = (float*)d_out;

    float* buf = nullptr;
    cudaGetSymbolAddress((void**)&buf, g_buf);
    bf16* XH   = (bf16*)(buf + OFF_XH);
    bf16* XL   = (bf16*)(buf + OFF_XL);
    float* QKV = buf + OFF_QKV;
    bf16* QKH  = (bf16*)(buf + OFF_QKH);
    bf16* QKL  = (bf16*)(buf + OFF_QKL);
    float* S   = buf + OFF_S;          // bf16 storage
    bf16* VTH  = (bf16*)(buf + OFF_VTH);
    bf16* VTL  = (bf16*)(buf + OFF_VTL);
    float* RS  = buf + OFF_RS;
    float* O1  = buf + OFF_O1;
    bf16* O1H  = (bf16*)(buf + OFF_O1H);
    bf16* O1L  = (bf16*)(buf + OFF_O1L);
    float* AO  = buf + OFF_AO;
    bf16* AOH  = (bf16*)(buf + OFF_AOH);
    bf16* AOL  = (bf16*)(buf + OFF_AOL);
    float* E   = buf + OFF_E;          // bf16 storage
    float* CAT = buf + OFF_CAT;
    bf16* CQH  = (bf16*)(buf + OFF_CQH);
    bf16* CQL  = (bf16*)(buf + OFF_CQL);
    float* LG  = buf + OFF_LG;
    float* SOFF = buf + OFF_SOFF;
    float* EOFF = buf + OFF_EOFF;
    float* AL  = buf + OFF_AL;
    float* BEp = buf + OFF_BE;
    float* Avec = buf + OFF_A;
    float* Bvec = buf + OFF_B;
    float* qbias = buf + OFF_QBIAS;
    float* pool = buf + OFF_POOL;
    float* QPT = buf + OFF_QPT;
    float* WC  = buf + OFF_WC;
    bf16* WPH  = (bf16*)(buf + OFF_WPH);
    bf16* WPL  = (bf16*)(buf + OFF_WPL);
    float* PB  = buf + OFF_PB;
    bf16* INWH = (bf16*)(buf + OFF_INWH);
    bf16* INWL = (bf16*)(buf + OFF_INWL);
    bf16* OWH  = (bf16*)(buf + OFF_OWH);
    bf16* OWL  = (bf16*)(buf + OFF_OWL);
    bf16* RW2H = (bf16*)(buf + OFF_RW2H);
    bf16* RW2L = (bf16*)(buf + OFF_RW2L);
    float* W56 = buf + OFF_W56;
    float* misc = buf + OFF_MISC;

    // ---- weight-stage precomputes (independent; overlap) ----
    k_qpt<<<dim3(16, 16), dim3(32, 8)>>>(qp_w, QPT);
    k_ab<<<1, 512>>>(in_w, qp_w, qp_b, in_b, Avec, Bvec, qbias);
    k_split<<<(3 * SD * SD / 4 + 255) / 256, 256>>>(in_w, INWH, INWL, 3 * SD * SD / 4);
    k_split<<<(SD * SD / 4 + 255) / 256, 256>>>(out_w, OWH, OWL, SD * SD / 4);
    k_split<<<(SNL * 200 * 128 / 4 + 255) / 256, 256>>>(ref_w2, RW2H, RW2L,
                                                        SNL * 200 * 128 / 4);
    tgemm<0, 0, 0><<<dim3(8, 4, 1), 256>>>(SD, SD, SD, in_w, nullptr, SD, 0,
                                           QPT, nullptr, SD, 0, nullptr, WC, SD, 0,
                                           1.f, 1, nullptr, 0, nullptr, nullptr, nullptr);
    k_pack<<<(NCAT * SD + 255) / 256, 256>>>(in_w, in_b, WC, qbias, ref_w1, ref_b1,
                                             WPH, WPL, PB, W56);

    // ---- data path ----
    k_x<<<(SN * SD / 4 + 255) / 256, 256>>>(ne, tp, W_time, b_time, XH, XL, pool, RS);

    // QKV = X @ in_w^T + in_b
    tgemm<0, 1, 1><<<dim3(24, 12, 1), 256>>>(SN, 3 * SD, SD, XH, XL, SD, 0,
                                             INWH, INWL, SD, 0, in_b,
                                             QKV, 3 * SD, 0, 1.f, 1,
                                             nullptr, 0, nullptr, nullptr, nullptr);
    // split Q|K cols of QKV
    k_split_st<<<(SN * 1024 / 4 + 255) / 256, 256>>>(QKV, 3 * SD, QKH, QKL, SN * 1024 / 4);
    // S(bf16) = exp(Q @ K^T * ISQ); row-sums into RS
    tgemm<1, 1, 1><<<dim3(24, 12, SH), 256>>>(SN, SN, SDH, QKH, QKL, 1024, SDH,
                                              QKH + 512, QKL + 512, 1024, SDH, nullptr,
                                              S, SN, (long)SN * SN, ISQ, 1,
                                              RS, SN, nullptr, nullptr, nullptr);
    k_vt<<<dim3(SN / 32, SDH / 32, SH), dim3(32, 8)>>>(QKV, VTH, VTL);
    k_init2<<<(SN * SD + 255) / 256, 256>>>(O1, AO, out_b);

    // O1 = (1/RS) * S(bf16 exact) @ VT^T  (split-K 4)
    tgemm<2, 2, 1><<<dim3(2, 12, SH * 4), 256>>>(SN, SDH, SN, S, nullptr, SN, (long)SN * SN,
                                                 VTH, VTL, SN, (long)SDH * SN, nullptr,
                                                 O1, SD, SDH, 1.f, 4,
                                                 RS, SN, nullptr, nullptr, nullptr);
    k_split<<<(SN * SD / 4 + 255) / 256, 256>>>(O1, O1H, O1L, SN * SD / 4);
    // AO = O1 @ out_w^T + out_b  (split-K 2)
    tgemm<0, 1, 1><<<dim3(8, 12, 2), 256>>>(SN, SD, SD, O1H, O1L, SD, 0,
                                            OWH, OWL, SD, 0, nullptr,
                                            AO, SD, 0, 1.f, 2,
                                            nullptr, 0, nullptr, nullptr, nullptr);
    k_split<<<(SN * SD / 4 + 255) / 256, 256>>>(AO, AOH, AOL, SN * SD / 4);

    k_pool<<<12, 512>>>(AO, pool);
    k_cls<<<1, 128>>>(pool, ic_w1, ic_b1, ic_w2, ic_b2, out, out_size);
    k_tmm<<<1, 256>>>(tp, misc);

    // CAT = AO @ WP^T + PB
    tgemm<0, 1, 1><<<dim3(22, 12, 1), 256>>>(SN, NCAT, SD, AOH, AOL, SD, 0,
                                             WPH, WPL, SD, 0, PB,
                                             CAT, NCAT, 0, 1.f, 1,
                                             nullptr, 0, nullptr, nullptr, nullptr);
    // split K2|QB cols of CAT
    k_split_st<<<(SN * 1024 / 4 + 255) / 256, 256>>>(CAT, NCAT, CQH, CQL, SN * 1024 / 4);
    // E(bf16) = exp(QB @ K2^T * ISQ)
    tgemm<1, 1, 1><<<dim3(24, 12, SH), 256>>>(SN, SN, SDH, CQH + 512, CQL + 512, 1024, SDH,
                                              CQH, CQL, 1024, SDH, nullptr,
                                              E, SN, (long)SN * SN, ISQ, 1,
                                              nullptr, 0, nullptr, nullptr, nullptr);

    k_alphabeta<<<dim3(6, SH), 256>>>(Avec, Bvec, CAT, NCAT, AL, BEp);

    float* HBc = CAT + 2 * SD;
    for (int l = 0; l < SNL; l++) {
        // logits = relu(HB_l + s*w5 + e*w6) @ ref_w2_l^T + ref_b2_l (5 intervals)
        tgemm<3, 0, 1><<<dim3(4, 12, SNI), 256>>>(SN, 200, 128, HBc + l * 128, nullptr,
                                                  NCAT, 0,
                                                  RW2H + (long)l * 200 * 128,
                                                  RW2L + (long)l * 200 * 128, 128, 0,
                                                  ref_b2 + l * 200, LG, 200, (long)SN * 200,
                                                  1.f, 1, nullptr, 0,
                                                  W56 + l * 128, W56 + SNL * 128 + l * 128,
                                                  misc);
        k_soff<<<SNI * SN, 64>>>(LG, wp, SOFF, EOFF);
        k_accum2<<<dim3(SN / 16, SH), 512>>>((const bf16*)E, AL, BEp,
                                             SOFF, EOFF, misc, (SN / 16) * SH);
    }

    k_outb<<<1, 32>>>(misc, out, out_size);
}

// round 17
// speedup vs baseline: 1.0683x; 1.0683x over previous
#include <cuda_runtime.h>
#include <cuda_bf16.h>
#include <math.h>

#define SN 1536        // sequence length
#define SD 512         // model dim
#define SH 4           // heads
#define SDH 128        // head dim
#define SNI 5
#define SNL 3
#define QPW_LD 514     // D+2
#define NCAT 1408      // 512 (K2) + 512 (QB) + 3*128 (HB)
#define ISQ 0.0883883476483184405f  // 1/sqrt(128)

typedef unsigned int u32;

// ---------------- static scratch ----------------
// S and E are bf16: sizes given in floats (half the element count)
#define SZ_X     (SN*SD)
#define SZ_QKV   (SN*3*SD)
#define SZ_S     (SH*SN*SN/2)
#define SZ_O1    (SN*SD)
#define SZ_AO    (SN*SD)
#define SZ_E     (SH*SN*SN/2)
#define SZ_VT    (SH*SDH*SN)
#define SZ_RS    (SH*SN)
#define SZ_CAT   (SN*NCAT)
#define SZ_LG    (SNI*SN*200)
#define SZ_SOFF  (SNI*SN)
#define SZ_EOFF  (SNI*SN)
#define SZ_AL    (SH*SN)
#define SZ_BE    (SH*SN)
#define SZ_A     (SD)
#define SZ_B     (SD)
#define SZ_QBIAS (SD)
#define SZ_POOL  (SD)
#define SZ_QPT   (SD*SD)
#define SZ_WC    (SD*SD)
#define SZ_WP    (NCAT*SD)
#define SZ_PB    (NCAT)
#define SZ_W56   (2*SNL*128)
#define SZ_MISC  (32)

#define OFF_X     0
#define OFF_QKV   (OFF_X + SZ_X)
#define OFF_S     (OFF_QKV + SZ_QKV)
#define OFF_O1    (OFF_S + SZ_S)
#define OFF_AO    (OFF_O1 + SZ_O1)
#define OFF_E     (OFF_AO + SZ_AO)
#define OFF_VT    (OFF_E + SZ_E)
#define OFF_RS    (OFF_VT + SZ_VT)
#define OFF_CAT   (OFF_RS + SZ_RS)
#define OFF_LG    (OFF_CAT + SZ_CAT)
#define OFF_SOFF  (OFF_LG + SZ_LG)
#define OFF_EOFF  (OFF_SOFF + SZ_SOFF)
#define OFF_AL    (OFF_EOFF + SZ_EOFF)
#define OFF_BE    (OFF_AL + SZ_AL)
#define OFF_A     (OFF_BE + SZ_BE)
#define OFF_B     (OFF_A + SZ_A)
#define OFF_QBIAS (OFF_B + SZ_B)
#define OFF_POOL  (OFF_QBIAS + SZ_QBIAS)
#define OFF_QPT   (OFF_POOL + SZ_POOL)
#define OFF_WC    (OFF_QPT + SZ_QPT)
#define OFF_WP    (OFF_WC + SZ_WC)
#define OFF_PB    (OFF_WP + SZ_WP)
#define OFF_W56   (OFF_PB + SZ_PB)
#define OFF_MISC  (OFF_W56 + SZ_W56)
#define BUF_TOTAL (OFF_MISC + SZ_MISC)

__device__ float g_buf[BUF_TOTAL];

// misc: 0 tmin, 1 tmax, [2..6] start, [7..11] end, [12..16] ds, [17..21] de, 22 counter

// ---------------- MMA helpers ----------------
__device__ __forceinline__ u32 smem_u32(const void* p) {
    u32 a;
    asm("{ .reg .u64 t; cvta.to.shared.u64 t, %1; cvt.u32.u64 %0, t; }" : "=r"(a) : "l"(p));
    return a;
}
__device__ __forceinline__ void ldsm4(u32* r, u32 addr) {
    asm volatile("ldmatrix.sync.aligned.m8n8.x4.shared.b16 {%0,%1,%2,%3}, [%4];"
                 : "=r"(r[0]), "=r"(r[1]), "=r"(r[2]), "=r"(r[3]) : "r"(addr));
}
__device__ __forceinline__ void mma16816(float* c, const u32* a, const u32* b) {
    asm volatile(
        "mma.sync.aligned.m16n8k16.row.col.f32.bf16.bf16.f32 "
        "{%0,%1,%2,%3}, {%4,%5,%6,%7}, {%8,%9}, {%0,%1,%2,%3};"
        : "+f"(c[0]), "+f"(c[1]), "+f"(c[2]), "+f"(c[3])
        : "r"(a[0]), "r"(a[1]), "r"(a[2]), "r"(a[3]), "r"(b[0]), "r"(b[1]));
}
__device__ __forceinline__ void split4(float4 v, uint2& hi, uint2& lo) {
    __nv_bfloat16 h0 = __float2bfloat16_rn(v.x), h1 = __float2bfloat16_rn(v.y),
                  h2 = __float2bfloat16_rn(v.z), h3 = __float2bfloat16_rn(v.w);
    __nv_bfloat162 hp0 = __halves2bfloat162(h0, h1), hp1 = __halves2bfloat162(h2, h3);
    __nv_bfloat162 lp0 = __floats2bfloat162_rn(v.x - __bfloat162float(h0),
                                               v.y - __bfloat162float(h1));
    __nv_bfloat162 lp1 = __floats2bfloat162_rn(v.z - __bfloat162float(h2),
                                               v.w - __bfloat162float(h3));
    hi = make_uint2(*(u32*)&hp0, *(u32*)&hp1);
    lo = make_uint2(*(u32*)&lp0, *(u32*)&lp1);
}
__device__ __forceinline__ uint2 hi4(float4 v) {
    __nv_bfloat162 hp0 = __floats2bfloat162_rn(v.x, v.y);
    __nv_bfloat162 hp1 = __floats2bfloat162_rn(v.z, v.w);
    return make_uint2(*(u32*)&hp0, *(u32*)&hp1);
}

// ---------------- tensor-core NT GEMM (HMMA bf16) ----------------
// MODE 0: plain fp32 A/B 3-term (bias if ksplit==1, else atomic into pre-init C)
// MODE 1: C(bf16) = exp(scale*acc), 3-term; atomic fp32 row-sums into rsbuf.
// MODE 2: C += (scale / rsbuf[r]) * acc  (split-K atomic, 3-term)
// MODE 3: fp32, A-load transform relu(A + s*hb5 + e*hb6), bias store, 3-term
// MODE 4: A exact bf16 -> 2-term; epilogue like MODE 2.
// MODE 5: 1-term bf16 (scores); epilogue like MODE 1.
#define LDT 40
template<int MODE>
__device__ __forceinline__ float4 ldA4(const float* p, int kcol,
                                       const float* hb5, const float* hb6,
                                       float s, float e) {
    float4 v = *(const float4*)p;
    if (MODE == 3) {
        float4 w5 = *(const float4*)(hb5 + kcol);
        float4 w6 = *(const float4*)(hb6 + kcol);
        v.x = fmaxf(v.x + s * w5.x + e * w6.x, 0.f);
        v.y = fmaxf(v.y + s * w5.y + e * w6.y, 0.f);
        v.z = fmaxf(v.z + s * w5.z + e * w6.z, 0.f);
        v.w = fmaxf(v.w + s * w5.w + e * w6.w, 0.f);
    }
    return v;
}

template<int MODE>
__global__ void __launch_bounds__(256)
tgemm(int M, int N, int K,
      const float* __restrict__ A, int lda, long sA,
      const float* __restrict__ B, int ldb, long sB,
      const float* __restrict__ bias,
      float* __restrict__ C, int ldc, long sC,
      float scale, int ksplit,
      float* __restrict__ rsbuf, long sRS, int alignB,
      const float* __restrict__ hb5, const float* __restrict__ hb6,
      const float* __restrict__ misc) {
    constexpr bool ALO = (MODE != 4 && MODE != 5);   // A lo-plane present
    constexpr bool BLO = (MODE != 5);                // B lo-plane present
    constexpr bool EXP = (MODE == 1 || MODE == 5);   // exp + bf16-store epilogue

    __shared__ __nv_bfloat16 sA_[2][128 * LDT];
    __shared__ __nv_bfloat16 sB_[2][64 * LDT];

    int batch = blockIdx.z / ksplit;
    int kz = blockIdx.z % ksplit;
    int Kc = K / ksplit;
    int kbeg = kz * Kc;
    const __nv_bfloat16* Ab = nullptr;
    if (MODE == 4) Ab = (const __nv_bfloat16*)A + (long)batch * sA;
    else A += (long)batch * sA;
    B += (long)batch * sB;
    __nv_bfloat16* Cb = nullptr;
    if (EXP) Cb = (__nv_bfloat16*)C + (long)batch * sC;
    else C += (long)batch * sC;
    int brow = blockIdx.y * 128, bcol = blockIdx.x * 64;

    float hs = 0.f, he = 0.f;
    if (MODE == 3) { hs = misc[2 + batch]; he = misc[7 + batch]; }

    int tid = threadIdx.x;
    int wid = tid >> 5, lane = tid & 31;
    int wm = (wid & 3) * 32;
    int wn = (wid >> 2) * 32;

    u32 aBase[2] = { smem_u32(sA_[0]), smem_u32(sA_[1]) };
    u32 bBase[2] = { smem_u32(sB_[0]), smem_u32(sB_[1]) };

    int rowsel = (lane & 7) + ((lane >> 3) & 1) * 8;
    int ksel = (lane >> 4) * 8;

    float acc[2][4][4];
#pragma unroll
    for (int mi = 0; mi < 2; mi++)
#pragma unroll
        for (int ni = 0; ni < 4; ni++)
#pragma unroll
            for (int j = 0; j < 4; j++) acc[mi][ni][j] = 0.f;

    float4 pa[4], pb[2];
    uint2 pa4[4];
#pragma unroll
    for (int i = 0; i < 4; i++) {
        int idx = tid + i * 256;
        int row = idx >> 3, col = (idx & 7) * 4;
        if (MODE == 4)
            pa4[i] = *(const uint2*)(Ab + (long)(brow + row) * lda + kbeg + col);
        else
            pa[i] = ldA4<MODE>(A + (long)(brow + row) * lda + kbeg + col, kbeg + col,
                               hb5, hb6, hs, he);
    }
#pragma unroll
    for (int i = 0; i < 2; i++) {
        int idx = tid + i * 256;
        int row = idx >> 3, col = (idx & 7) * 4;
        int rB = bcol + row;
        if (rB < N) {
            const float* bp = B + (long)rB * ldb + kbeg + col;
            pb[i] = alignB ? *(const float4*)bp
                           : make_float4(bp[0], bp[1], bp[2], bp[3]);
        } else pb[i] = make_float4(0.f, 0.f, 0.f, 0.f);
    }

    for (int kc = 0; kc < Kc; kc += 32) {
#pragma unroll
        for (int i = 0; i < 4; i++) {
            int idx = tid + i * 256;
            int row = idx >> 3, col = (idx & 7) * 4;
            if (MODE == 4) {
                *(uint2*)&sA_[0][row * LDT + col] = pa4[i];
            } else if (MODE == 5) {
                *(uint2*)&sA_[0][row * LDT + col] = hi4(pa[i]);
            } else {
                uint2 hi, lo;
                split4(pa[i], hi, lo);
                *(uint2*)&sA_[0][row * LDT + col] = hi;
                *(uint2*)&sA_[1][row * LDT + col] = lo;
            }
        }
#pragma unroll
        for (int i = 0; i < 2; i++) {
            int idx = tid + i * 256;
            int row = idx >> 3, col = (idx & 7) * 4;
            if (MODE == 5) {
                *(uint2*)&sB_[0][row * LDT + col] = hi4(pb[i]);
            } else {
                uint2 hi, lo;
                split4(pb[i], hi, lo);
                *(uint2*)&sB_[0][row * LDT + col] = hi;
                *(uint2*)&sB_[1][row * LDT + col] = lo;
            }
        }
        __syncthreads();

        int kn = kbeg + kc + 32;
        if (kc + 32 < Kc) {
#pragma unroll
            for (int i = 0; i < 4; i++) {
                int idx = tid + i * 256;
                int row = idx >> 3, col = (idx & 7) * 4;
                if (MODE == 4)
                    pa4[i] = *(const uint2*)(Ab + (long)(brow + row) * lda + kn + col);
                else
                    pa[i] = ldA4<MODE>(A + (long)(brow + row) * lda + kn + col, kn + col,
                                       hb5, hb6, hs, he);
            }
#pragma unroll
            for (int i = 0; i < 2; i++) {
                int idx = tid + i * 256;
                int row = idx >> 3, col = (idx & 7) * 4;
                int rB = bcol + row;
                if (rB < N) {
                    const float* bp = B + (long)rB * ldb + kn + col;
                    pb[i] = alignB ? *(const float4*)bp
                                   : make_float4(bp[0], bp[1], bp[2], bp[3]);
                } else pb[i] = make_float4(0.f, 0.f, 0.f, 0.f);
            }
        }

#pragma unroll
        for (int ks = 0; ks < 32; ks += 16) {
            u32 ahi[2][4], alo[2][4], bhi[4][2], blo[4][2];
#pragma unroll
            for (int mi = 0; mi < 2; mi++) {
                u32 off = ((wm + mi * 16 + rowsel) * LDT + ks + ksel) * 2;
                ldsm4(ahi[mi], aBase[0] + off);
                if (ALO) ldsm4(alo[mi], aBase[1] + off);
            }
#pragma unroll
            for (int nj = 0; nj < 2; nj++) {
                u32 off = ((wn + nj * 16 + rowsel) * LDT + ks + ksel) * 2;
                u32 t0[4], t1[4];
                ldsm4(t0, bBase[0] + off);
                if (BLO) ldsm4(t1, bBase[1] + off);
                bhi[2 * nj][0] = t0[0]; bhi[2 * nj][1] = t0[2];
                bhi[2 * nj + 1][0] = t0[1]; bhi[2 * nj + 1][1] = t0[3];
                if (BLO) {
                    blo[2 * nj][0] = t1[0]; blo[2 * nj][1] = t1[2];
                    blo[2 * nj + 1][0] = t1[1]; blo[2 * nj + 1][1] = t1[3];
                }
            }
#pragma unroll
            for (int mi = 0; mi < 2; mi++)
#pragma unroll
                for (int ni = 0; ni < 4; ni++) {
                    mma16816(acc[mi][ni], ahi[mi], bhi[ni]);
                    if (BLO) mma16816(acc[mi][ni], ahi[mi], blo[ni]);
                    if (ALO) mma16816(acc[mi][ni], alo[mi], bhi[ni]);
                }
        }
        __syncthreads();
    }

    // epilogue
    int g = lane >> 2, t = lane & 3;
#pragma unroll
    for (int mi = 0; mi < 2; mi++) {
        int r0 = brow + wm + mi * 16 + g;
        int r1 = r0 + 8;
        float s0 = scale, s1 = scale;
        if (MODE == 2 || MODE == 4) {
            s0 = scale / rsbuf[sRS * batch + r0];
            s1 = scale / rsbuf[sRS * batch + r1];
        }
        float sum0 = 0.f, sum1 = 0.f;
#pragma unroll
        for (int ni = 0; ni < 4; ni++) {
            int cc = bcol + wn + ni * 8 + 2 * t;
            float v00 = acc[mi][ni][0] * s0, v01 = acc[mi][ni][1] * s0;
            float v10 = acc[mi][ni][2] * s1, v11 = acc[mi][ni][3] * s1;
            if (EXP) {
                v00 = __expf(v00); v01 = __expf(v01);
                v10 = __expf(v10); v11 = __expf(v11);
                sum0 += v00 + v01; sum1 += v10 + v11;
                if (cc < N) {
                    __nv_bfloat162 p0 = __floats2bfloat162_rn(v00, v01);
                    __nv_bfloat162 p1 = __floats2bfloat162_rn(v10, v11);
                    *(u32*)&Cb[(long)r0 * ldc + cc] = *(u32*)&p0;
                    *(u32*)&Cb[(long)r1 * ldc + cc] = *(u32*)&p1;
                }
            } else if (MODE == 2 || MODE == 4 || ksplit > 1) {
                if (cc < N) {
                    atomicAdd(&C[(long)r0 * ldc + cc], v00);
                    atomicAdd(&C[(long)r1 * ldc + cc], v10);
                }
                if (cc + 1 < N) {
                    atomicAdd(&C[(long)r0 * ldc + cc + 1], v01);
                    atomicAdd(&C[(long)r1 * ldc + cc + 1], v11);
                }
            } else {
                if (bias) {
                    if (cc < N) { v00 += bias[cc]; v10 += bias[cc]; }
                    if (cc + 1 < N) { v01 += bias[cc + 1]; v11 += bias[cc + 1]; }
                }
                if (cc < N) { C[(long)r0 * ldc + cc] = v00; C[(long)r1 * ldc + cc] = v10; }
                if (cc + 1 < N) { C[(long)r0 * ldc + cc + 1] = v01; C[(long)r1 * ldc + cc + 1] = v11; }
            }
        }
        if (EXP && rsbuf) {
            sum0 += __shfl_xor_sync(0xffffffffu, sum0, 1);
            sum0 += __shfl_xor_sync(0xffffffffu, sum0, 2);
            sum1 += __shfl_xor_sync(0xffffffffu, sum1, 1);
            sum1 += __shfl_xor_sync(0xffffffffu, sum1, 2);
            if (t == 0) {
                atomicAdd(&rsbuf[sRS * batch + r0], sum0);
                atomicAdd(&rsbuf[sRS * batch + r1], sum1);
            }
        }
    }
}

// ---------------- small kernels ----------------

__global__ void k_x(const float* __restrict__ ne, const float* __restrict__ tp,
                    const float* __restrict__ wt, const float* __restrict__ bt,
                    float* __restrict__ X, float* __restrict__ pool,
                    float* __restrict__ RS) {
    int idx = blockIdx.x * 256 + threadIdx.x;
    if (idx < SN * SD) {
        int i = idx >> 9, d = idx & 511;
        X[idx] = ne[idx] + tp[i] * wt[d] + bt[d];
    }
    if (idx < SD) pool[idx] = 0.f;
    if (idx < SH * SN) RS[idx] = 0.f;
}

__global__ void k_qpt(const float* __restrict__ qp_w, float* __restrict__ QPT) {
    __shared__ float t[32][33];
    int d0 = blockIdx.x * 32, j0 = blockIdx.y * 32;
    int x = threadIdx.x, y0 = threadIdx.y;
#pragma unroll
    for (int dy = 0; dy < 32; dy += 8) {
        int d = d0 + y0 + dy;
        t[y0 + dy][x] = qp_w[(long)d * QPW_LD + j0 + x];
    }
    __syncthreads();
#pragma unroll
    for (int dy = 0; dy < 32; dy += 8) {
        int j = j0 + y0 + dy;
        QPT[(long)j * SD + d0 + x] = t[x][y0 + dy];
    }
}

__global__ void k_ab(const float* __restrict__ in_w, const float* __restrict__ qp_w,
                     const float* __restrict__ qp_b, const float* __restrict__ in_b,
                     float* __restrict__ a, float* __restrict__ b,
                     float* __restrict__ qbias) {
    __shared__ float u[SD], v[SD], w[SD];
    int tid = threadIdx.x;  // 512
    u[tid] = qp_w[(long)tid * QPW_LD + 512];
    v[tid] = qp_w[(long)tid * QPW_LD + 513];
    w[tid] = qp_b[tid];
    __syncthreads();
    float sa = 0.f, sb = 0.f, sq = 0.f;
    const float* wr = in_w + (long)tid * SD;
    for (int d = 0; d < SD; d++) {
        float ww = wr[d];
        sa += ww * u[d];
        sb += ww * v[d];
        sq += ww * w[d];
    }
    a[tid] = sa; b[tid] = sb; qbias[tid] = in_b[tid] + sq;
}

__global__ void k_pack(const float* __restrict__ in_w, const float* __restrict__ in_b,
                       const float* __restrict__ WC, const float* __restrict__ qbias,
                       const float* __restrict__ ref_w1, const float* __restrict__ ref_b1,
                       float* __restrict__ WP, float* __restrict__ PB,
                       float* __restrict__ w56) {
    int idx = blockIdx.x * 256 + threadIdx.x;
    if (idx < NCAT * SD) {
        int n = idx >> 9, d = idx & 511;
        float v;
        if (n < SD) v = in_w[(long)(SD + n) * SD + d];
        else if (n < 2 * SD) v = WC[(long)(n - SD) * SD + d];
        else v = ref_w1[(long)(n - 2 * SD) * QPW_LD + d];
        WP[idx] = v;
    }
    if (idx < NCAT) {
        float v;
        if (idx < SD) v = in_b[SD + idx];
        else if (idx < 2 * SD) v = qbias[idx - SD];
        else v = ref_b1[idx - 2 * SD];
        PB[idx] = v;
    }
    if (idx < SNL * 128) {
        w56[idx] = ref_w1[(long)idx * QPW_LD + 512];
        w56[SNL * 128 + idx] = ref_w1[(long)idx * QPW_LD + 513];
    }
}

__global__ void k_init2(float* __restrict__ O1, float* __restrict__ AO,
                        const float* __restrict__ out_b) {
    int idx = blockIdx.x * 256 + threadIdx.x;
    if (idx < SN * SD) {
        O1[idx] = 0.f;
        AO[idx] = out_b[idx & 511];
    }
}

__global__ void k_vt(const float* __restrict__ QKV, float* __restrict__ VT) {
    __shared__ float t[32][33];
    int h = blockIdx.z;
    int k0 = blockIdx.x * 32, n0 = blockIdx.y * 32;
    int x = threadIdx.x, y0 = threadIdx.y;
#pragma unroll
    for (int dy = 0; dy < 32; dy += 8) {
        int k = k0 + y0 + dy;
        t[y0 + dy][x] = QKV[(long)k * (3 * SD) + 2 * SD + h * SDH + n0 + x];
    }
    __syncthreads();
#pragma unroll
    for (int dy = 0; dy < 32; dy += 8) {
        int n = n0 + y0 + dy;
        VT[((long)h * SDH + n) * SN + k0 + x] = t[x][y0 + dy];
    }
}

__global__ void k_pool(const float* __restrict__ AO, float* __restrict__ pool) {
    int d = threadIdx.x;  // 512
    int r0 = blockIdx.x * 128;
    float s = 0.f;
    for (int r = 0; r < 128; r++) s += AO[(long)(r0 + r) * SD + d];
    atomicAdd(&pool[d], s);
}

__global__ void k_cls(const float* __restrict__ pool,
                      const float* __restrict__ w1, const float* __restrict__ b1,
                      const float* __restrict__ w2, const float* __restrict__ b2,
                      float* __restrict__ out, int out_size) {
    __shared__ float pv[SD];
    __shared__ float h1[128];
    __shared__ float lg[5];
    int tid = threadIdx.x;  // 128
    for (int i = tid; i < SD; i += 128) pv[i] = pool[i] * (1.f / SN);
    __syncthreads();
    {
        float r = b1[tid];
        const float* wr = w1 + (long)tid * SD;
        for (int d = 0; d < SD; d++) r += wr[d] * pv[d];
        h1[tid] = fmaxf(r, 0.f);
    }
    __syncthreads();
    if (tid < 5) {
        float r = b2[tid];
        const float* wr = w2 + (long)tid * 128;
        for (int j = 0; j < 128; j++) r += wr[j] * h1[j];
        lg[tid] = r;
    }
    __syncthreads();
    if (tid == 0) {
        int arg = 0;
        float best = lg[0];
        for (int i = 1; i < 5; i++)
            if (lg[i] > best) { best = lg[i]; arg = i; }
        int num = arg + 1;
        if (out_size >= 15)
            for (int i = 0; i < 5; i++) out[10 + i] = (i < num) ? 1.f : 0.f;
    }
}

__global__ void k_tmm(const float* __restrict__ tp, float* __restrict__ misc) {
    __shared__ float mn[256], mx[256];
    int tid = threadIdx.x;
    float a = 1e30f, b = -1e30f;
    for (int i = tid; i < SN; i += 256) {
        float v = tp[i];
        a = fminf(a, v);
        b = fmaxf(b, v);
    }
    mn[tid] = a; mx[tid] = b;
    __syncthreads();
    for (int s = 128; s > 0; s >>= 1) {
        if (tid < s) {
            mn[tid] = fminf(mn[tid], mn[tid + s]);
            mx[tid] = fmaxf(mx[tid], mx[tid + s]);
        }
        __syncthreads();
    }
    if (tid == 0) {
        float tmin = mn[0], tmax = mx[0];
        misc[0] = tmin; misc[1] = tmax;
        float step = (tmax - tmin) / 5.f;
        for (int i = 0; i < 5; i++) {
            misc[2 + i] = tmin + i * step;
            misc[7 + i] = tmin + (i + 1) * step;
        }
        misc[22] = 0.f;
    }
    if (tid >= 32 && tid < 42) misc[12 + (tid - 32)] = 0.f;
}

__global__ void k_alphabeta(const float* __restrict__ a, const float* __restrict__ b,
                            const float* __restrict__ K2, int ldk,
                            float* __restrict__ alpha, float* __restrict__ beta) {
    int h = blockIdx.y;
    int k = blockIdx.x * 256 + threadIdx.x;
    __shared__ float a_s[SDH], b_s[SDH];
    if (threadIdx.x < SDH) {
        a_s[threadIdx.x] = a[h * SDH + threadIdx.x];
        b_s[threadIdx.x] = b[h * SDH + threadIdx.x];
    }
    __syncthreads();
    if (k >= SN) return;
    const float* kr = K2 + (long)k * ldk + h * SDH;
    float sa = 0.f, sb = 0.f;
    for (int j = 0; j < SDH; j++) {
        float kv = kr[j];
        sa += kv * a_s[j];
        sb += kv * b_s[j];
    }
    alpha[h * SN + k] = sa * ISQ;
    beta[h * SN + k] = sb * ISQ;
}

__global__ void k_soff(const float* __restrict__ LG, const float* __restrict__ wp,
                       float* __restrict__ SOFF, float* __restrict__ EOFF) {
    int r = blockIdx.x;
    int warp = threadIdx.x >> 5, lane = threadIdx.x & 31;
    const float* row = LG + (long)r * 200 + warp * 100;
    float m = -1e30f;
    for (int k = lane; k < 100; k += 32) m = fmaxf(m, row[k]);
    for (int o = 16; o > 0; o >>= 1) m = fmaxf(m, __shfl_xor_sync(0xffffffffu, m, o));
    float s = 0.f, d = 0.f;
    for (int k = lane; k < 100; k += 32) {
        float e = __expf(row[k] - m);
        s += e;
        d += e * wp[k];
    }
    for (int o = 16; o > 0; o >>= 1) {
        s += __shfl_xor_sync(0xffffffffu, s, o);
        d += __shfl_xor_sync(0xffffffffu, d, o);
    }
    if (lane == 0) {
        float val = d / s;
        if (warp == 0) SOFF[r] = val; else EOFF[r] = val;
    }
}

__global__ void k_accum2(const __nv_bfloat16* __restrict__ E,
                         const float* __restrict__ AL, const float* __restrict__ BE,
                         const float* __restrict__ SOFF, const float* __restrict__ EOFF,
                         float* __restrict__ misc, int nblocks) {
    int h = blockIdx.y;
    int warp = threadIdx.x >> 5, lane = threadIdx.x & 31;
    int q = blockIdx.x * 16 + warp;
    __shared__ float Gs[15][256];
    __shared__ float se[10];
    __shared__ int lastflag;
    if (threadIdx.x < 10) se[threadIdx.x] = misc[2 + threadIdx.x];
    const __nv_bfloat16* Erow = E + (long)h * SN * SN + (long)q * SN;
    float acc[15];
#pragma unroll
    for (int c = 0; c < 15; c++) acc[c] = 0.f;
    for (int k0 = 0; k0 < SN; k0 += 256) {
        __syncthreads();
        for (int idx = threadIdx.x; idx < 5 * 256; idx += 512) {
            int i = idx >> 8, kk = idx & 255;
            int k = k0 + kk;
            float al = AL[h * SN + k], be = BE[h * SN + k];
            float g = __expf(se[i] * al + se[5 + i] * be);
            Gs[3 * i][kk] = g;
            Gs[3 * i + 1][kk] = g * SOFF[i * SN + k];
            Gs[3 * i + 2][kk] = g * EOFF[i * SN + k];
        }
        __syncthreads();
#pragma unroll
        for (int s = 0; s < 8; s++) {
            int kk = lane + 32 * s;
            float ev = __bfloat162float(Erow[k0 + kk]);
#pragma unroll
            for (int c = 0; c < 15; c++) acc[c] += ev * Gs[c][kk];
        }
    }
#pragma unroll
    for (int c = 0; c < 15; c++)
        for (int o = 16; o > 0; o >>= 1)
            acc[c] += __shfl_xor_sync(0xffffffffu, acc[c], o);
    if (lane == 0) {
#pragma unroll
        for (int i = 0; i < 5; i++) {
            float inv = 0.25f / acc[3 * i];
            atomicAdd(&misc[12 + i], acc[3 * i + 1] * inv);
            atomicAdd(&misc[17 + i], acc[3 * i + 2] * inv);
        }
    }
    __syncthreads();
    if (threadIdx.x == 0) {
        __threadfence();
        u32 old = atomicAdd((u32*)&misc[22], 1u);
        lastflag = (old == (u32)(nblocks - 1)) ? 1 : 0;
    }
    __syncthreads();
    if (lastflag && threadIdx.x < 5) {
        int t = threadIdx.x;
        misc[2 + t] += misc[12 + t];
        misc[7 + t] += misc[17 + t];
        misc[12 + t] = 0.f;
        misc[17 + t] = 0.f;
        if (t == 0) misc[22] = 0.f;
    }
}

__global__ void k_outb(const float* __restrict__ misc, float* __restrict__ out, int out_size) {
    int t = threadIdx.x;
    if (t < 5 && out_size >= 10) {
        out[2 * t] = misc[2 + t];
        out[2 * t + 1] = misc[7 + t];
    }
}

// ---------------- host ----------------
extern "C" void kernel_launch(void* const* d_in, const int* in_sizes, int n_in,
                              void* d_out, int out_size) {
    const float* ne     = (const float*)d_in[0];
    const float* tp     = (const float*)d_in[1];
    const float* W_time = (const float*)d_in[3];
    const float* b_time = (const float*)d_in[4];
    const float* in_w   = (const float*)d_in[5];
    const float* in_b   = (const float*)d_in[6];
    const float* out_w  = (const float*)d_in[7];
    const float* out_b  = (const float*)d_in[8];
    const float* ic_w1  = (const float*)d_in[9];
    const float* ic_b1  = (const float*)d_in[10];
    const float* ic_w2  = (const float*)d_in[11];
    const float* ic_b2  = (const float*)d_in[12];
    const float* ref_w1 = (const float*)d_in[13];
    const float* ref_b1 = (const float*)d_in[14];
    const float* ref_w2 = (const float*)d_in[15];
    const float* ref_b2 = (const float*)d_in[16];
    const float* wp     = (const float*)d_in[17];
    const float* qp_w   = (const float*)d_in[18];
    const float* qp_b   = (const float*)d_in[19];
    float* out = (float*)d_out;

    float* buf = nullptr;
    cudaGetSymbolAddress((void**)&buf, g_buf);
    float* X     = buf + OFF_X;
    float* QKV   = buf + OFF_QKV;
    float* S     = buf + OFF_S;    // bf16 storage
    float* O1    = buf + OFF_O1;
    float* AO    = buf + OFF_AO;
    float* E     = buf + OFF_E;    // bf16 storage
    float* VT    = buf + OFF_VT;
    float* RS    = buf + OFF_RS;
    float* CAT   = buf + OFF_CAT;
    float* LG    = buf + OFF_LG;
    float* SOFF  = buf + OFF_SOFF;
    float* EOFF  = buf + OFF_EOFF;
    float* AL    = buf + OFF_AL;
    float* BEp   = buf + OFF_BE;
    float* Avec  = buf + OFF_A;
    float* Bvec  = buf + OFF_B;
    float* qbias = buf + OFF_QBIAS;
    float* pool  = buf + OFF_POOL;
    float* QPT   = buf + OFF_QPT;
    float* WC    = buf + OFF_WC;
    float* WP    = buf + OFF_WP;
    float* PB    = buf + OFF_PB;
    float* W56   = buf + OFF_W56;
    float* misc  = buf + OFF_MISC;

    // weight-only precomputes
    k_qpt<<<dim3(16, 16), dim3(32, 8)>>>(qp_w, QPT);
    k_ab<<<1, 512>>>(in_w, qp_w, qp_b, in_b, Avec, Bvec, qbias);
    tgemm<0><<<dim3(8, 4, 1), 256>>>(SD, SD, SD, in_w, SD, 0, QPT, SD, 0,
                                     nullptr, WC, SD, 0, 1.f, 1,
                                     nullptr, 0, 1, nullptr, nullptr, nullptr);
    k_pack<<<(NCAT * SD + 255) / 256, 256>>>(in_w, in_b, WC, qbias, ref_w1, ref_b1,
                                             WP, PB, W56);

    // X = ne + t*Wt^T + bt ; zero pool + RS
    k_x<<<(SN * SD + 255) / 256, 256>>>(ne, tp, W_time, b_time, X, pool, RS);

    // QKV = X @ in_w^T + in_b
    tgemm<0><<<dim3(24, 12, 1), 256>>>(SN, 3 * SD, SD, X, SD, 0, in_w, SD, 0,
                                       in_b, QKV, 3 * SD, 0, 1.f, 1,
                                       nullptr, 0, 1, nullptr, nullptr, nullptr);
    // S_h(bf16) = exp(Q_h @ K_h^T / sqrt(DH)); fp32 row-sums into RS  (1-term scores)
    tgemm<5><<<dim3(24, 12, SH), 256>>>(SN, SN, SDH, QKV, 3 * SD, SDH,
                                        QKV + SD, 3 * SD, SDH, nullptr,
                                        S, SN, (long)SN * SN, ISQ, 1,
                                        RS, SN, 1, nullptr, nullptr, nullptr);
    k_vt<<<dim3(SN / 32, SDH / 32, SH), dim3(32, 8)>>>(QKV, VT);
    k_init2<<<(SN * SD + 255) / 256, 256>>>(O1, AO, out_b);

    // O1_h = (1/RS_h[r]) * S_h(bf16) @ VT_h^T  (split-K 4, 2-term)
    tgemm<4><<<dim3(2, 12, SH * 4), 256>>>(SN, SDH, SN, S, SN, (long)SN * SN,
                                           VT, SN, (long)SDH * SN, nullptr,
                                           O1, SD, SDH, 1.f, 4,
                                           RS, SN, 1, nullptr, nullptr, nullptr);
    // AO = O1 @ out_w^T + out_b  (split-K 4)
    tgemm<0><<<dim3(8, 12, 4), 256>>>(SN, SD, SD, O1, SD, 0, out_w, SD, 0,
                                      nullptr, AO, SD, 0, 1.f, 4,
                                      nullptr, 0, 1, nullptr, nullptr, nullptr);

    k_pool<<<12, 512>>>(AO, pool);
    k_cls<<<1, 128>>>(pool, ic_w1, ic_b1, ic_w2, ic_b2, out, out_size);
    k_tmm<<<1, 256>>>(tp, misc);

    // CAT = AO @ WP^T + PB   (K2 | QB | HB0..2) — single mega-GEMM
    tgemm<0><<<dim3(22, 12, 1), 256>>>(SN, NCAT, SD, AO, SD, 0, WP, SD, 0,
                                       PB, CAT, NCAT, 0, 1.f, 1,
                                       nullptr, 0, 1, nullptr, nullptr, nullptr);
    float* K2c = CAT;
    float* QBc = CAT + SD;
    float* HBc = CAT + 2 * SD;

    // E(bf16) = exp(QB_h @ K2_h^T / sqrt(DH))  (1-term scores)
    tgemm<5><<<dim3(24, 12, SH), 256>>>(SN, SN, SDH, QBc, NCAT, SDH, K2c, NCAT, SDH,
                                        nullptr, E, SN, (long)SN * SN, ISQ, 1,
                                        nullptr, 0, 1, nullptr, nullptr, nullptr);

    k_alphabeta<<<dim3(6, SH), 256>>>(Avec, Bvec, K2c, NCAT, AL, BEp);

    for (int l = 0; l < SNL; l++) {
        // logits = relu(HB_l + s*w5 + e*w6) @ ref_w2_l^T + ref_b2_l (5 intervals)
        tgemm<3><<<dim3(4, 12, SNI), 256>>>(SN, 200, 128, HBc + l * 128, NCAT, 0,
                                            ref_w2 + (long)l * 200 * 128, 128, 0,
                                            ref_b2 + l * 200, LG, 200, (long)SN * 200,
                                            1.f, 1, nullptr, 0, 1,
                                            W56 + l * 128, W56 + SNL * 128 + l * 128, misc);
        k_soff<<<SNI * SN, 64>>>(LG, wp, SOFF, EOFF);
        k_accum2<<<dim3(SN / 16, SH), 512>>>((const __nv_bfloat16*)E, AL, BEp,
                                             SOFF, EOFF, misc, (SN / 16) * SH);
    }

    k_outb<<<1, 32>>>(misc, out, out_size);
}